// round 9
// baseline (speedup 1.0000x reference)
#include <cuda_runtime.h>
#include <cuda_fp16.h>
#include <math.h>

#define MAXN 100000
#define F 32
#define CAP 80   // max in-degree bucket (Poisson lambda=16 -> P(deg>=80) ~ 7e-29)

// Scratch (no allocs allowed). Feature buffers stored as fp16 (uint2 = 4 halves/lane).
__device__ uint2 g_H1[MAXN * 8];     // hs1 = (x@W1)*dinv, half, row = 64B
__device__ uint2 g_H2[MAXN * 8];     // hs2 = (h1@W2)*dinv, half
__device__ int   g_adj[MAXN * CAP];  // fixed-capacity adjacency by dst
__device__ int   g_cnt[MAXN];        // in-degree / bump pointer
__device__ float g_dinv[MAXN];
__device__ int   g_max[F];           // float-as-int max (relu => >= 0)
__device__ int   g_is64;

// ---------------------------------------------------------------------------
__global__ void k_init(const int* __restrict__ ew, int n) {
    int i = blockIdx.x * blockDim.x + threadIdx.x;
    if (i < n) g_cnt[i] = 0;
    if (i < F) g_max[i] = 0;
    if (blockIdx.x == 0 && threadIdx.x == 0) {
        int all_zero = 1;
        #pragma unroll 1
        for (int k = 0; k < 128; k++)
            if (ew[2 * k + 1] != 0) { all_zero = 0; break; }
        g_is64 = all_zero;  // int64 ids < 2^31 -> all odd words zero
    }
}

__device__ __forceinline__ int load_idx(const int* __restrict__ ew, int is64, long long pos) {
    return is64 ? ew[2 * pos] : ew[pos];   // low word of int64
}

// Build bucketed adjacency: adj[dst][pos] = src. One atomic bump per edge.
__global__ void k_fill(const int* __restrict__ ew, int E) {
    int e = blockIdx.x * blockDim.x + threadIdx.x;
    if (e >= E) return;
    int is64 = g_is64;
    int src = load_idx(ew, is64, e);
    int dst = load_idx(ew, is64, (long long)E + e);
    int pos = atomicAdd(&g_cnt[dst], 1);
    if (pos < CAP) g_adj[dst * CAP + pos] = src;
}

// ---------------------------------------------------------------------------
// Layer-1 transform: dinv = rsqrt(deg+1); H1[i,:] = half((x[i,:] @ W1) * dinv).
__global__ void k_lin1(const float* __restrict__ x, const float* __restrict__ W1, int n) {
    __shared__ float sW[8 * F];
    int t = threadIdx.x;
    if (t < 8 * F) sW[t] = W1[t];
    __syncthreads();
    int i = blockIdx.x * (blockDim.x >> 5) + (t >> 5);
    int j = t & 31;
    if (i >= n) return;
    float di = rsqrtf((float)(g_cnt[i] + 1));
    if (j == 0) g_dinv[i] = di;
    float xv = (j < 8) ? x[i * 8 + j] : 0.f;
    float acc = 0.f;
    #pragma unroll
    for (int k = 0; k < 8; k++)
        acc += __shfl_sync(0xffffffffu, xv, k) * sW[k * F + j];
    ((__half*)g_H1)[i * F + j] = __float2half(acc * di);
}

// ---------------------------------------------------------------------------
// Gather core: warp = 4 neighbor-slots x 8 feature-lanes (uint2 = 4 halves/lane).
// Each slot owns a CONTIGUOUS 16B-aligned quarter of the neighbor list, so one
// int4 load supplies 4 neighbor ids (1 adj LDG per 16 neighbors warp-wide).
// The 4 gathered rows are summed pairwise in fp16 (6 HADD2), converted to fp32
// once per chunk. Final shfl.xor reduce folds the 4 slots.
__device__ __forceinline__ float4 gather_h(const uint2* __restrict__ A,
                                           const int* __restrict__ adj,
                                           int deg, int i, int slot, int fg) {
    float4 acc = make_float4(0.f, 0.f, 0.f, 0.f);
    if (slot == 0) {   // self loop, counted once
        uint2 v = A[i * 8 + fg];
        float2 lo = __half22float2(*(__half2*)&v.x);
        float2 hi = __half22float2(*(__half2*)&v.y);
        acc.x = lo.x; acc.y = lo.y; acc.z = hi.x; acc.w = hi.y;
    }
    int qs = ((deg + 15) >> 4) << 2;          // per-slot stride, multiple of 4
    int beg = slot * qs;
    int end = min(deg, beg + qs);
    const uint2 z2 = make_uint2(0u, 0u);
    #pragma unroll 2
    for (int e = beg; e < end; e += 4) {
        int4 s4 = *(const int4*)(adj + e);    // 16B aligned (beg,e multiples of 4)
        int m = end - e;
        uint2 b0 = A[s4.x * 8 + fg];
        uint2 b1 = (m > 1) ? A[s4.y * 8 + fg] : z2;
        uint2 b2 = (m > 2) ? A[s4.z * 8 + fg] : z2;
        uint2 b3 = (m > 3) ? A[s4.w * 8 + fg] : z2;
        __half2 p0 = __hadd2(*(__half2*)&b0.x, *(__half2*)&b1.x);
        __half2 p1 = __hadd2(*(__half2*)&b0.y, *(__half2*)&b1.y);
        __half2 q0 = __hadd2(*(__half2*)&b2.x, *(__half2*)&b3.x);
        __half2 q1 = __hadd2(*(__half2*)&b2.y, *(__half2*)&b3.y);
        __half2 r0 = __hadd2(p0, q0);
        __half2 r1 = __hadd2(p1, q1);
        float2 lo = __half22float2(r0);
        float2 hi = __half22float2(r1);
        acc.x += lo.x; acc.y += lo.y; acc.z += hi.x; acc.w += hi.y;
    }
    #pragma unroll
    for (int off = 8; off <= 16; off <<= 1) {
        acc.x += __shfl_xor_sync(0xffffffffu, acc.x, off);
        acc.y += __shfl_xor_sync(0xffffffffu, acc.y, off);
        acc.z += __shfl_xor_sync(0xffffffffu, acc.z, off);
        acc.w += __shfl_xor_sync(0xffffffffu, acc.w, off);
    }
    return acc;   // full neighbor sum for features [4fg..4fg+3], all lanes
}

// ---------------------------------------------------------------------------
// Fused: gather + relu(*dinv + b1) + 32x32 W2 transform (*dinv) -> H2 (half).
__global__ void k_agg1(const float* __restrict__ b1, const float* __restrict__ W2, int n) {
    __shared__ float sW[F * F];
    int t = threadIdx.x;
    for (int k = t; k < F * F; k += blockDim.x) sW[k] = W2[k];
    __syncthreads();
    int lane = t & 31, w = t >> 5;
    int slot = lane >> 3, fg = lane & 7;
    int i = blockIdx.x * (blockDim.x >> 5) + w;
    if (i >= n) return;
    int deg = min(g_cnt[i], CAP);
    const int* adj = g_adj + i * CAP;
    float4 acc = gather_h(g_H1, adj, deg, i, slot, fg);
    float di = g_dinv[i];
    float4 bb = ((const float4*)b1)[fg];
    float4 h;
    h.x = fmaxf(acc.x * di + bb.x, 0.f);
    h.y = fmaxf(acc.y * di + bb.y, 0.f);
    h.z = fmaxf(acc.z * di + bb.z, 0.f);
    h.w = fmaxf(acc.w * di + bb.w, 0.f);
    // transform: out[j] = sum_k h_k * W2[k][j]; feature k=4q+c lives in lane q comp c.
    int j = lane;
    float o = 0.f;
    #pragma unroll
    for (int q = 0; q < 8; q++) {
        float hx = __shfl_sync(0xffffffffu, h.x, q);
        float hy = __shfl_sync(0xffffffffu, h.y, q);
        float hz = __shfl_sync(0xffffffffu, h.z, q);
        float hw = __shfl_sync(0xffffffffu, h.w, q);
        o += hx * sW[(4 * q + 0) * F + j];
        o += hy * sW[(4 * q + 1) * F + j];
        o += hz * sW[(4 * q + 2) * F + j];
        o += hw * sW[(4 * q + 3) * F + j];
    }
    ((__half*)g_H2)[i * F + j] = __float2half(o * di);
}

// ---------------------------------------------------------------------------
// Fused: gather + relu(*dinv + b2) + block max pool -> global atomicMax.
__global__ void k_agg2(const float* __restrict__ b2, int n) {
    __shared__ float sm[8][F];
    int t = threadIdx.x;
    int lane = t & 31, w = t >> 5;
    int slot = lane >> 3, fg = lane & 7;
    int i = blockIdx.x * (blockDim.x >> 5) + w;
    float4 h = make_float4(0.f, 0.f, 0.f, 0.f);
    if (i < n) {
        int deg = min(g_cnt[i], CAP);
        const int* adj = g_adj + i * CAP;
        float4 acc = gather_h(g_H2, adj, deg, i, slot, fg);
        float di = g_dinv[i];
        float4 bb = ((const float4*)b2)[fg];
        h.x = fmaxf(acc.x * di + bb.x, 0.f);
        h.y = fmaxf(acc.y * di + bb.y, 0.f);
        h.z = fmaxf(acc.z * di + bb.z, 0.f);
        h.w = fmaxf(acc.w * di + bb.w, 0.f);
    }
    if (slot == 0) {
        sm[w][fg * 4 + 0] = h.x;
        sm[w][fg * 4 + 1] = h.y;
        sm[w][fg * 4 + 2] = h.z;
        sm[w][fg * 4 + 3] = h.w;
    }
    __syncthreads();
    if (w == 0) {
        float mm = sm[0][lane];
        #pragma unroll
        for (int k = 1; k < 8; k++) mm = fmaxf(mm, sm[k][lane]);
        atomicMax(&g_max[lane], __float_as_int(mm));
    }
}

// ---------------------------------------------------------------------------
__global__ void k_fc(const float* __restrict__ fcW, const float* __restrict__ fcb,
                     float* __restrict__ out) {
    if (threadIdx.x != 0) return;
    float g[F];
    #pragma unroll
    for (int j = 0; j < F; j++) g[j] = __int_as_float(g_max[j]);
    float lg[5];
    float mx = -1e30f;
    #pragma unroll
    for (int c = 0; c < 5; c++) {
        float a = fcb[c];
        #pragma unroll
        for (int j = 0; j < F; j++) a += g[j] * fcW[j * 5 + c];
        lg[c] = a;
        mx = fmaxf(mx, a);
    }
    float sum = 0.f;
    #pragma unroll
    for (int c = 0; c < 5; c++) sum += expf(lg[c] - mx);
    float l = logf(sum) + mx;
    #pragma unroll
    for (int c = 0; c < 5; c++) out[c] = lg[c] - l;
}

// ---------------------------------------------------------------------------
extern "C" void kernel_launch(void* const* d_in, const int* in_sizes, int n_in,
                              void* d_out, int out_size) {
    const float* x   = (const float*)d_in[0];
    const int*   ew  = (const int*)d_in[1];
    const float* W1  = (const float*)d_in[2];
    const float* b1  = (const float*)d_in[3];
    const float* W2  = (const float*)d_in[4];
    const float* b2  = (const float*)d_in[5];
    const float* fcW = (const float*)d_in[6];
    const float* fcb = (const float*)d_in[7];
    float* out = (float*)d_out;

    int n = in_sizes[0] / 8;      // 100000
    int E = in_sizes[1] / 2;      // 1600000

    k_init<<<(n + 255) / 256, 256>>>(ew, n);
    k_fill<<<(E + 255) / 256, 256>>>(ew, E);
    k_lin1<<<(n + 7) / 8, 256>>>(x, W1, n);
    k_agg1<<<(n + 7) / 8, 256>>>(b1, W2, n);
    k_agg2<<<(n + 7) / 8, 256>>>(b2, n);
    k_fc<<<1, 32>>>(fcW, fcb, out);
}

// round 10
// speedup vs baseline: 1.3547x; 1.3547x over previous
#include <cuda_runtime.h>
#include <cuda_fp16.h>
#include <math.h>

#define MAXN 100000
#define F 32
#define CAP 80   // max in-degree bucket (Poisson lambda=16 -> P(deg>=80) ~ 7e-29)

// Scratch (no allocs allowed). Feature buffers stored as fp16, row = 64B = 4x uint4.
__device__ uint4 g_H1[MAXN * 4];     // hs1 = (x@W1)*dinv, half
__device__ uint4 g_H2[MAXN * 4];     // hs2 = (h1@W2)*dinv, half
__device__ int   g_adj[MAXN * CAP];  // fixed-capacity adjacency by dst
__device__ int   g_cnt[MAXN];        // in-degree / bump pointer
__device__ float g_dinv[MAXN];
__device__ int   g_max[F];           // float-as-int max (relu => >= 0)
__device__ int   g_is64;

// ---------------------------------------------------------------------------
__global__ void k_init(const int* __restrict__ ew, int n) {
    int i = blockIdx.x * blockDim.x + threadIdx.x;
    if (i < n) g_cnt[i] = 0;
    if (i < F) g_max[i] = 0;
    if (blockIdx.x == 0 && threadIdx.x == 0) {
        int all_zero = 1;
        #pragma unroll 1
        for (int k = 0; k < 128; k++)
            if (ew[2 * k + 1] != 0) { all_zero = 0; break; }
        g_is64 = all_zero;  // int64 ids < 2^31 -> all odd words zero
    }
}

__device__ __forceinline__ int load_idx(const int* __restrict__ ew, int is64, long long pos) {
    return is64 ? ew[2 * pos] : ew[pos];   // low word of int64
}

// Build bucketed adjacency: adj[dst][pos] = src. One atomic bump per edge.
__global__ void k_fill(const int* __restrict__ ew, int E) {
    int e = blockIdx.x * blockDim.x + threadIdx.x;
    if (e >= E) return;
    int is64 = g_is64;
    int src = load_idx(ew, is64, e);
    int dst = load_idx(ew, is64, (long long)E + e);
    int pos = atomicAdd(&g_cnt[dst], 1);
    if (pos < CAP) g_adj[dst * CAP + pos] = src;
}

// ---------------------------------------------------------------------------
// Layer-1 transform: dinv = rsqrt(deg+1); H1[i,:] = half((x[i,:] @ W1) * dinv).
__global__ void k_lin1(const float* __restrict__ x, const float* __restrict__ W1, int n) {
    __shared__ float sW[8 * F];
    int t = threadIdx.x;
    if (t < 8 * F) sW[t] = W1[t];
    __syncthreads();
    int i = blockIdx.x * (blockDim.x >> 5) + (t >> 5);
    int j = t & 31;
    if (i >= n) return;
    float di = rsqrtf((float)(g_cnt[i] + 1));
    if (j == 0) g_dinv[i] = di;
    float xv = (j < 8) ? x[i * 8 + j] : 0.f;
    float acc = 0.f;
    #pragma unroll
    for (int k = 0; k < 8; k++)
        acc += __shfl_sync(0xffffffffu, xv, k) * sW[k * F + j];
    ((__half*)g_H1)[i * F + j] = __float2half(acc * di);
}

// ---------------------------------------------------------------------------
// Gather core: warp = 8 neighbor-slots x 4 feature-lanes. Each lane loads a
// uint4 (= 8 halves, features [8fl..8fl+7]) -> one LDG.128 covers 8 rows/warp.
// Slots take neighbors slot, slot+8, slot+16, ... (balanced to +-1).
// Depth-4 preload: up to 32 independent rows in flight per warp. Preloaded
// pairs summed with hadd2, then fp32 accumulate. 3-round shfl.xor folds slots.
struct Acc8 { float2 a[4]; };

__device__ __forceinline__ void acc_u4(Acc8& s, uint4 v) {
    float2 t;
    t = __half22float2(*(__half2*)&v.x); s.a[0].x += t.x; s.a[0].y += t.y;
    t = __half22float2(*(__half2*)&v.y); s.a[1].x += t.x; s.a[1].y += t.y;
    t = __half22float2(*(__half2*)&v.z); s.a[2].x += t.x; s.a[2].y += t.y;
    t = __half22float2(*(__half2*)&v.w); s.a[3].x += t.x; s.a[3].y += t.y;
}

__device__ __forceinline__ uint4 hadd_u4(uint4 p, uint4 q) {
    uint4 r;
    *(__half2*)&r.x = __hadd2(*(__half2*)&p.x, *(__half2*)&q.x);
    *(__half2*)&r.y = __hadd2(*(__half2*)&p.y, *(__half2*)&q.y);
    *(__half2*)&r.z = __hadd2(*(__half2*)&p.z, *(__half2*)&q.z);
    *(__half2*)&r.w = __hadd2(*(__half2*)&p.w, *(__half2*)&q.w);
    return r;
}

__device__ __forceinline__ Acc8 gather_h(const uint4* __restrict__ A,
                                         const int* __restrict__ adj,
                                         int deg, int i, int slot, int fl) {
    Acc8 s;
    s.a[0] = s.a[1] = s.a[2] = s.a[3] = make_float2(0.f, 0.f);
    if (slot == 0) acc_u4(s, A[i * 4 + fl]);   // self loop, counted once
    const uint4 z4 = make_uint4(0u, 0u, 0u, 0u);
    #pragma unroll 1
    for (int e = slot; e < deg; e += 32) {
        uint4 b0 = A[adj[e] * 4 + fl];
        uint4 b1 = (e + 8  < deg) ? A[adj[e + 8]  * 4 + fl] : z4;
        uint4 b2 = (e + 16 < deg) ? A[adj[e + 16] * 4 + fl] : z4;
        uint4 b3 = (e + 24 < deg) ? A[adj[e + 24] * 4 + fl] : z4;
        acc_u4(s, hadd_u4(b0, b1));   // fp16 pair-add (adds ~1 half-ulp level)
        acc_u4(s, hadd_u4(b2, b3));
    }
    #pragma unroll
    for (int off = 4; off <= 16; off <<= 1) {
        #pragma unroll
        for (int c = 0; c < 4; c++) {
            s.a[c].x += __shfl_xor_sync(0xffffffffu, s.a[c].x, off);
            s.a[c].y += __shfl_xor_sync(0xffffffffu, s.a[c].y, off);
        }
    }
    return s;   // full neighbor sum for features [8fl..8fl+7], all lanes
}

// ---------------------------------------------------------------------------
// Fused: gather + relu(*dinv + b1) + 32x32 W2 transform (*dinv) -> H2 (half).
__global__ void k_agg1(const float* __restrict__ b1, const float* __restrict__ W2, int n) {
    __shared__ float sW[F * F];
    int t = threadIdx.x;
    for (int k = t; k < F * F; k += blockDim.x) sW[k] = W2[k];
    __syncthreads();
    int lane = t & 31, w = t >> 5;
    int slot = lane >> 2, fl = lane & 3;
    int i = blockIdx.x * (blockDim.x >> 5) + w;
    if (i >= n) return;
    int deg = min(g_cnt[i], CAP);
    const int* adj = g_adj + i * CAP;
    Acc8 s = gather_h(g_H1, adj, deg, i, slot, fl);
    float di = g_dinv[i];
    float h[8];
    #pragma unroll
    for (int c = 0; c < 4; c++) {
        h[2 * c]     = fmaxf(s.a[c].x * di + b1[fl * 8 + 2 * c],     0.f);
        h[2 * c + 1] = fmaxf(s.a[c].y * di + b1[fl * 8 + 2 * c + 1], 0.f);
    }
    // transform: out[j] = sum_k h_k * W2[k][j]; feature k=8q+c lives in lane q (slot 0).
    int j = lane;
    float o = 0.f;
    #pragma unroll
    for (int q = 0; q < 4; q++) {
        #pragma unroll
        for (int c = 0; c < 8; c++) {
            float hv = __shfl_sync(0xffffffffu, h[c], q);
            o += hv * sW[(8 * q + c) * F + j];
        }
    }
    ((__half*)g_H2)[i * F + j] = __float2half(o * di);
}

// ---------------------------------------------------------------------------
// Fused: gather + relu(*dinv + b2) + block max pool -> global atomicMax.
__global__ void k_agg2(const float* __restrict__ b2, int n) {
    __shared__ float sm[8][F];
    int t = threadIdx.x;
    int lane = t & 31, w = t >> 5;
    int slot = lane >> 2, fl = lane & 3;
    int i = blockIdx.x * (blockDim.x >> 5) + w;
    if (i < n) {
        int deg = min(g_cnt[i], CAP);
        const int* adj = g_adj + i * CAP;
        Acc8 s = gather_h(g_H2, adj, deg, i, slot, fl);
        float di = g_dinv[i];
        if (slot == 0) {
            #pragma unroll
            for (int c = 0; c < 4; c++) {
                sm[w][fl * 8 + 2 * c]     = fmaxf(s.a[c].x * di + b2[fl * 8 + 2 * c],     0.f);
                sm[w][fl * 8 + 2 * c + 1] = fmaxf(s.a[c].y * di + b2[fl * 8 + 2 * c + 1], 0.f);
            }
        }
    } else if (slot == 0) {
        #pragma unroll
        for (int c = 0; c < 8; c++) sm[w][fl * 8 + c] = 0.f;
    }
    __syncthreads();
    if (w == 0) {
        float mm = sm[0][lane];
        #pragma unroll
        for (int k = 1; k < 8; k++) mm = fmaxf(mm, sm[k][lane]);
        atomicMax(&g_max[lane], __float_as_int(mm));
    }
}

// ---------------------------------------------------------------------------
__global__ void k_fc(const float* __restrict__ fcW, const float* __restrict__ fcb,
                     float* __restrict__ out) {
    if (threadIdx.x != 0) return;
    float g[F];
    #pragma unroll
    for (int j = 0; j < F; j++) g[j] = __int_as_float(g_max[j]);
    float lg[5];
    float mx = -1e30f;
    #pragma unroll
    for (int c = 0; c < 5; c++) {
        float a = fcb[c];
        #pragma unroll
        for (int j = 0; j < F; j++) a += g[j] * fcW[j * 5 + c];
        lg[c] = a;
        mx = fmaxf(mx, a);
    }
    float sum = 0.f;
    #pragma unroll
    for (int c = 0; c < 5; c++) sum += expf(lg[c] - mx);
    float l = logf(sum) + mx;
    #pragma unroll
    for (int c = 0; c < 5; c++) out[c] = lg[c] - l;
}

// ---------------------------------------------------------------------------
extern "C" void kernel_launch(void* const* d_in, const int* in_sizes, int n_in,
                              void* d_out, int out_size) {
    const float* x   = (const float*)d_in[0];
    const int*   ew  = (const int*)d_in[1];
    const float* W1  = (const float*)d_in[2];
    const float* b1  = (const float*)d_in[3];
    const float* W2  = (const float*)d_in[4];
    const float* b2  = (const float*)d_in[5];
    const float* fcW = (const float*)d_in[6];
    const float* fcb = (const float*)d_in[7];
    float* out = (float*)d_out;

    int n = in_sizes[0] / 8;      // 100000
    int E = in_sizes[1] / 2;      // 1600000

    k_init<<<(n + 255) / 256, 256>>>(ew, n);
    k_fill<<<(E + 255) / 256, 256>>>(ew, E);
    k_lin1<<<(n + 7) / 8, 256>>>(x, W1, n);
    k_agg1<<<(n + 7) / 8, 256>>>(b1, W2, n);
    k_agg2<<<(n + 7) / 8, 256>>>(b2, n);
    k_fc<<<1, 32>>>(fcW, fcb, out);
}

// round 12
// speedup vs baseline: 1.5038x; 1.1101x over previous
#include <cuda_runtime.h>
#include <cuda_fp16.h>
#include <math.h>

#define MAXN 100000
#define F 32
#define CAP 80   // max in-degree bucket (Poisson lambda=16 -> P(deg>=80) ~ 7e-29)

// Scratch (no allocs allowed). Feature buffers stored as fp16 (uint2 = 4 halves/lane).
__device__ uint2 g_H1[MAXN * 8];     // hs1 = (x@W1)*dinv, half, row = 64B
__device__ uint2 g_H2[MAXN * 8];     // hs2 = (h1@W2)*dinv, half
__device__ int   g_adj[MAXN * CAP];  // fixed-capacity adjacency by dst (16B-aligned rows)
__device__ int   g_cnt[MAXN];        // in-degree / bump pointer
__device__ float g_dinv[MAXN];
__device__ int   g_max[F];           // float-as-int max (relu => >= 0)
__device__ int   g_is64;

// ---------------------------------------------------------------------------
__global__ void k_init(const int* __restrict__ ew, int n) {
    int i = blockIdx.x * blockDim.x + threadIdx.x;
    if (i < n) g_cnt[i] = 0;
    if (i < F) g_max[i] = 0;
    if (blockIdx.x == 0 && threadIdx.x == 0) {
        int all_zero = 1;
        #pragma unroll 1
        for (int k = 0; k < 128; k++)
            if (ew[2 * k + 1] != 0) { all_zero = 0; break; }
        g_is64 = all_zero;  // int64 ids < 2^31 -> all odd words zero
    }
}

__device__ __forceinline__ int load_idx(const int* __restrict__ ew, int is64, long long pos) {
    return is64 ? ew[2 * pos] : ew[pos];   // low word of int64
}

// Build bucketed adjacency: adj[dst][pos] = src. One atomic bump per edge.
// Unwritten tail entries stay 0 (valid id); gather masks their values anyway.
__global__ void k_fill(const int* __restrict__ ew, int E) {
    int e = blockIdx.x * blockDim.x + threadIdx.x;
    if (e >= E) return;
    int is64 = g_is64;
    int src = load_idx(ew, is64, e);
    int dst = load_idx(ew, is64, (long long)E + e);
    int pos = atomicAdd(&g_cnt[dst], 1);
    if (pos < CAP) g_adj[dst * CAP + pos] = src;
}

// ---------------------------------------------------------------------------
// Layer-1 transform: dinv = rsqrt(deg+1); H1[i,:] = half((x[i,:] @ W1) * dinv).
__global__ void __launch_bounds__(256) k_lin1(const float* __restrict__ x,
                                              const float* __restrict__ W1, int n) {
    __shared__ float sW[8 * F];
    int t = threadIdx.x;
    if (t < 8 * F) sW[t] = W1[t];
    __syncthreads();
    int i = blockIdx.x * (blockDim.x >> 5) + (t >> 5);
    int j = t & 31;
    if (i >= n) return;
    float di = rsqrtf((float)(g_cnt[i] + 1));
    if (j == 0) g_dinv[i] = di;
    float xv = (j < 8) ? x[i * 8 + j] : 0.f;
    float acc = 0.f;
    #pragma unroll
    for (int k = 0; k < 8; k++)
        acc += __shfl_sync(0xffffffffu, xv, k) * sW[k * F + j];
    ((__half*)g_H1)[i * F + j] = __float2half(acc * di);
}

// ---------------------------------------------------------------------------
// Gather core: warp = 4 neighbor-slots x 8 feature-lanes (uint2 = 4 halves).
// Chunked: each 16-neighbor chunk is split 4-contiguous per slot, so ONE int4
// LDG supplies the slot's 4 indices (1 idx load per 16 rows warp-wide, chunk-
// local balance). The 4 rows are tree-summed in fp16 (6 HADD2) and folded into
// the fp32 accumulator once per chunk. 2-round shfl.xor folds the 4 slots.
__device__ __forceinline__ __half2 u2h(unsigned v) { return *(__half2*)&v; }

__device__ __forceinline__ float4 gather_h(const uint2* __restrict__ A,
                                           const int* __restrict__ adj,
                                           int deg, int i, int slot, int fg) {
    float4 acc = make_float4(0.f, 0.f, 0.f, 0.f);
    if (slot == 0) {   // self loop, counted once
        uint2 v = A[i * 8 + fg];
        float2 lo = __half22float2(u2h(v.x));
        float2 hi = __half22float2(u2h(v.y));
        acc.x = lo.x; acc.y = lo.y; acc.z = hi.x; acc.w = hi.y;
    }
    const uint2 z2 = make_uint2(0u, 0u);
    #pragma unroll 2
    for (int base = 0; base < deg; base += 16) {
        int m = deg - base - 4 * slot;                     // valid rows this slot
        int4 s4 = *(const int4*)(adj + base + 4 * slot);   // 16B-aligned quad
        uint2 b0 = (m > 0) ? A[s4.x * 8 + fg] : z2;
        uint2 b1 = (m > 1) ? A[s4.y * 8 + fg] : z2;
        uint2 b2 = (m > 2) ? A[s4.z * 8 + fg] : z2;
        uint2 b3 = (m > 3) ? A[s4.w * 8 + fg] : z2;
        __half2 u0 = __hadd2(u2h(b0.x), u2h(b1.x));
        __half2 u1 = __hadd2(u2h(b2.x), u2h(b3.x));
        __half2 r0 = __hadd2(u0, u1);
        __half2 v0 = __hadd2(u2h(b0.y), u2h(b1.y));
        __half2 v1 = __hadd2(u2h(b2.y), u2h(b3.y));
        __half2 r1 = __hadd2(v0, v1);
        float2 lo = __half22float2(r0);
        float2 hi = __half22float2(r1);
        acc.x += lo.x; acc.y += lo.y; acc.z += hi.x; acc.w += hi.y;
    }
    #pragma unroll
    for (int off = 8; off <= 16; off <<= 1) {
        acc.x += __shfl_xor_sync(0xffffffffu, acc.x, off);
        acc.y += __shfl_xor_sync(0xffffffffu, acc.y, off);
        acc.z += __shfl_xor_sync(0xffffffffu, acc.z, off);
        acc.w += __shfl_xor_sync(0xffffffffu, acc.w, off);
    }
    return acc;   // full neighbor sum for features [4fg..4fg+3], all lanes
}

// ---------------------------------------------------------------------------
// Fused: gather + relu(*dinv + b1) + 32x32 W2 transform (*dinv) -> H2 (half).
// Transform reads h via smem broadcast (1 STS.128 + 8 LDS.128) instead of shfl.
__global__ void __launch_bounds__(256) k_agg1(const float* __restrict__ b1,
                                              const float* __restrict__ W2, int n) {
    __shared__ float sW[F * F];
    __shared__ float sh[8][F];
    int t = threadIdx.x;
    for (int k = t; k < F * F; k += blockDim.x) sW[k] = W2[k];
    __syncthreads();
    int lane = t & 31, w = t >> 5;
    int slot = lane >> 3, fg = lane & 7;
    int i = blockIdx.x * (blockDim.x >> 5) + w;
    if (i >= n) return;
    int deg = min(g_cnt[i], CAP);
    const int* adj = g_adj + i * CAP;
    float4 acc = gather_h(g_H1, adj, deg, i, slot, fg);
    float di = g_dinv[i];
    float4 bb = ((const float4*)b1)[fg];
    float4 h;
    h.x = fmaxf(acc.x * di + bb.x, 0.f);
    h.y = fmaxf(acc.y * di + bb.y, 0.f);
    h.z = fmaxf(acc.z * di + bb.z, 0.f);
    h.w = fmaxf(acc.w * di + bb.w, 0.f);
    if (slot == 0) *(float4*)&sh[w][fg * 4] = h;
    __syncwarp();
    int j = lane;
    float o = 0.f;
    #pragma unroll
    for (int q = 0; q < 8; q++) {
        float4 hq = *(const float4*)&sh[w][q * 4];   // uniform broadcast LDS.128
        o += hq.x * sW[(4 * q + 0) * F + j];
        o += hq.y * sW[(4 * q + 1) * F + j];
        o += hq.z * sW[(4 * q + 2) * F + j];
        o += hq.w * sW[(4 * q + 3) * F + j];
    }
    ((__half*)g_H2)[i * F + j] = __float2half(o * di);
}

// ---------------------------------------------------------------------------
// Fused: gather + relu(*dinv + b2) + block max pool -> global atomicMax.
__global__ void __launch_bounds__(256) k_agg2(const float* __restrict__ b2, int n) {
    __shared__ float sm[8][F];
    int t = threadIdx.x;
    int lane = t & 31, w = t >> 5;
    int slot = lane >> 3, fg = lane & 7;
    int i = blockIdx.x * (blockDim.x >> 5) + w;
    if (i < n) {
        int deg = min(g_cnt[i], CAP);
        const int* adj = g_adj + i * CAP;
        float4 acc = gather_h(g_H2, adj, deg, i, slot, fg);
        float di = g_dinv[i];
        float4 bb = ((const float4*)b2)[fg];
        if (slot == 0) {
            float4 h;
            h.x = fmaxf(acc.x * di + bb.x, 0.f);
            h.y = fmaxf(acc.y * di + bb.y, 0.f);
            h.z = fmaxf(acc.z * di + bb.z, 0.f);
            h.w = fmaxf(acc.w * di + bb.w, 0.f);
            *(float4*)&sm[w][fg * 4] = h;
        }
    } else if (slot == 0) {
        *(float4*)&sm[w][fg * 4] = make_float4(0.f, 0.f, 0.f, 0.f);
    }
    __syncthreads();
    if (w == 0) {
        float mm = sm[0][lane];
        #pragma unroll
        for (int k = 1; k < 8; k++) mm = fmaxf(mm, sm[k][lane]);
        atomicMax(&g_max[lane], __float_as_int(mm));
    }
}

// ---------------------------------------------------------------------------
__global__ void k_fc(const float* __restrict__ fcW, const float* __restrict__ fcb,
                     float* __restrict__ out) {
    if (threadIdx.x != 0) return;
    float g[F];
    #pragma unroll
    for (int j = 0; j < F; j++) g[j] = __int_as_float(g_max[j]);
    float lg[5];
    float mx = -1e30f;
    #pragma unroll
    for (int c = 0; c < 5; c++) {
        float a = fcb[c];
        #pragma unroll
        for (int j = 0; j < F; j++) a += g[j] * fcW[j * 5 + c];
        lg[c] = a;
        mx = fmaxf(mx, a);
    }
    float sum = 0.f;
    #pragma unroll
    for (int c = 0; c < 5; c++) sum += expf(lg[c] - mx);
    float l = logf(sum) + mx;
    #pragma unroll
    for (int c = 0; c < 5; c++) out[c] = lg[c] - l;
}

// ---------------------------------------------------------------------------
extern "C" void kernel_launch(void* const* d_in, const int* in_sizes, int n_in,
                              void* d_out, int out_size) {
    const float* x   = (const float*)d_in[0];
    const int*   ew  = (const int*)d_in[1];
    const float* W1  = (const float*)d_in[2];
    const float* b1  = (const float*)d_in[3];
    const float* W2  = (const float*)d_in[4];
    const float* b2  = (const float*)d_in[5];
    const float* fcW = (const float*)d_in[6];
    const float* fcb = (const float*)d_in[7];
    float* out = (float*)d_out;

    int n = in_sizes[0] / 8;      // 100000
    int E = in_sizes[1] / 2;      // 1600000

    k_init<<<(n + 255) / 256, 256>>>(ew, n);
    k_fill<<<(E + 255) / 256, 256>>>(ew, E);
    k_lin1<<<(n + 7) / 8, 256>>>(x, W1, n);
    k_agg1<<<(n + 7) / 8, 256>>>(b1, W2, n);
    k_agg2<<<(n + 7) / 8, 256>>>(b2, n);
    k_fc<<<1, 32>>>(fcW, fcb, out);
}